// round 15
// baseline (speedup 1.0000x reference)
#include <cuda_runtime.h>
#include <cuda_bf16.h>
#include <cuda_fp16.h>
#include <cstdint>
#include <stdint.h>
#include <math.h>

#define Nn 16
#define Cc 512
#define C4 128
#define QKC 16
#define LLEN 1024
#define EPSf 1e-5f
#define CONVK 2304          // 9 taps * 256 attn channels

// ---------------- scratch (device globals; no allocation allowed) ----------------
__device__ float g_qk[2 * 2 * Nn * QKC * LLEN];           // [q/k][pyr][b][qc][l]
__device__ __half g_attnh[(size_t)2 * Nn * LLEN * LLEN];  // [pyr][b][m][l] probs fp16
__device__ float g_y[Nn * Cc * LLEN];                     // conv output pre-BN
__device__ float g_stats[Cc * 2];
__device__ float g_mean[Nn * C4];
__device__ float g_wsum[9 * Cc * C4];
__device__ float g_contrib[Nn * 9 * Cc];
__device__ float g_sp4[Nn * Cc * 16];                     // pooled 4x4 per (b,c)
__device__ float g_rwT[2 * Cc * C4];                      // rce weights T [layer][c][out]
__device__ __half g_wh[Cc * CONVK];                       // fusion weight fp16 [co][tap*256+cc]
__device__ __half g_wv[C4 * Cc];                          // value weight fp16 [c][k]
__device__ __half g_xh[(size_t)Nn * LLEN * Cc];           // x transposed fp16 [b][l][c]
__device__ __half g_vh[Nn * C4 * LLEN];                   // V fp16 [b][c][l]
__device__ __half g_cth[(size_t)Nn * LLEN * 256];         // feat fp16 [b][pix][cc]

__device__ __forceinline__ int qk_idx(int g, int py, int b, int qc, int l) {
    return (((g * 2 + py) * Nn + b) * QKC + qc) * LLEN + l;
}

// ---------------- PTX helpers (legacy tensor path, sm_80+) ----------------
__device__ __forceinline__ uint32_t smem_u32(const void* p) {
    uint32_t a;
    asm("{ .reg .u64 t; cvta.to.shared.u64 t, %1; cvt.u32.u64 %0, t; }" : "=r"(a) : "l"(p));
    return a;
}
__device__ __forceinline__ void ldsm_x4(uint32_t& r0, uint32_t& r1, uint32_t& r2, uint32_t& r3,
                                        uint32_t addr) {
    asm volatile("ldmatrix.sync.aligned.m8n8.x4.shared.b16 {%0,%1,%2,%3}, [%4];"
                 : "=r"(r0), "=r"(r1), "=r"(r2), "=r"(r3) : "r"(addr));
}
__device__ __forceinline__ void ldsm_x2(uint32_t& r0, uint32_t& r1, uint32_t addr) {
    asm volatile("ldmatrix.sync.aligned.m8n8.x2.shared.b16 {%0,%1}, [%2];"
                 : "=r"(r0), "=r"(r1) : "r"(addr));
}
__device__ __forceinline__ void mma_f16(float* c, const uint32_t* a, const uint32_t* b) {
    asm volatile(
        "mma.sync.aligned.m16n8k16.row.col.f32.f16.f16.f32 "
        "{%0,%1,%2,%3}, {%4,%5,%6,%7}, {%8,%9}, {%0,%1,%2,%3};"
        : "+f"(c[0]), "+f"(c[1]), "+f"(c[2]), "+f"(c[3])
        : "r"(a[0]), "r"(a[1]), "r"(a[2]), "r"(a[3]), "r"(b[0]), "r"(b[1]));
}
__device__ __forceinline__ uint32_t swz(uint32_t boff) {
    return boff ^ ((boff >> 3) & 0x70);
}
__device__ __forceinline__ void cp16(uint32_t dst, const void* src, bool pred) {
    const int sz = pred ? 16 : 0;
    asm volatile("cp.async.cg.shared.global [%0], [%1], 16, %2;"
                 :: "r"(dst), "l"(src), "r"(sz) : "memory");
}
__device__ __forceinline__ void cp_commit() {
    asm volatile("cp.async.commit_group;" ::: "memory");
}
__device__ __forceinline__ void cp_wait1() {
    asm volatile("cp.async.wait_group 1;" ::: "memory");
}
__device__ __forceinline__ void cp_wait0() {
    asm volatile("cp.async.wait_group 0;" ::: "memory");
}
// FMA-pipe exp (x<=0): degree-5 Taylor of 2^f + exponent add. rel err ~2e-6.
__device__ __forceinline__ float fexp(float x) {
    float y = fmaxf(x * 1.44269504f, -80.f);
    float r = rintf(y);
    float f = y - r;
    float p = 1.3333558e-3f;
    p = fmaf(p, f, 9.6181291e-3f);
    p = fmaf(p, f, 5.5504109e-2f);
    p = fmaf(p, f, 2.4022651e-1f);
    p = fmaf(p, f, 6.9314718e-1f);
    p = fmaf(p, f, 1.0f);
    return __int_as_float(__float_as_int(p) + (((int)r) << 23));
}

// ---------------- K0a: transpose-convert x -> xh fp16 [b][l][c] -----------------
__global__ void k_xh(const float* __restrict__ x) {
    __shared__ float tile[32][33];
    const int b = blockIdx.z, c0 = blockIdx.y * 32, l0 = blockIdx.x * 32;
    const int t = threadIdx.x;
    const int col = t & 31, row = t >> 5;
    for (int r = row; r < 32; r += 8)
        tile[r][col] = x[((size_t)b * Cc + c0 + r) * LLEN + l0 + col];
    __syncthreads();
    for (int r = row; r < 32; r += 8)
        g_xh[((size_t)b * LLEN + l0 + r) * Cc + c0 + col] = __float2half(tile[col][r]);
}

// ---------------- K0: fused weight preprocessing (wv | rwt | wsplit | wsum) -----
__global__ void k_wprep(const float* __restrict__ value_w,
                        const float* __restrict__ rce_w,
                        const float* __restrict__ fw) {
    const int blk = blockIdx.x, t = threadIdx.x;
    if (blk < 256) {                                 // wv: 65536
        const int idx = blk * 256 + t;
        g_wv[idx] = __float2half(value_w[idx]);
    } else if (blk < 768) {                          // rwt: 131072
        const int idx = (blk - 256) * 256 + t;
        const int layer = idx >> 16;
        const int rest = idx & 65535;
        const int c = rest >> 7, out = rest & 127;
        g_rwT[idx] = rce_w[((layer + 1) * C4 + out) * Cc + c];
    } else if (blk < 5376) {                         // wsplit: 1179648
        const int idx = (blk - 768) * 256 + t;
        const int co = idx / CONVK, k = idx % CONVK;
        const int tap = k >> 8, cc = k & 255;
        g_wh[idx] = __float2half(fw[co * 3456 + 1152 + cc * 9 + tap]);
    } else {                                         // wsum: 65536 (co,ci) pairs
        const int idx = (blk - 5376) * 256 + t;
        const int co = idx >> 7, ci = idx & 127;
        float w[9];
#pragma unroll
        for (int k = 0; k < 9; k++) w[k] = fw[co * 3456 + ci * 9 + k];
#pragma unroll
        for (int rt = 0; rt < 3; rt++) {
            const int kylo = (rt == 0) ? 1 : 0, kyhi = (rt == 2) ? 1 : 2;
#pragma unroll
            for (int ct = 0; ct < 3; ct++) {
                const int kxlo = (ct == 0) ? 1 : 0, kxhi = (ct == 2) ? 1 : 2;
                float s = 0.f;
                for (int ky = kylo; ky <= kyhi; ky++)
                    for (int kx = kxlo; kx <= kxhi; kx++)
                        s += w[ky * 3 + kx];
                g_wsum[((rt * 3 + ct) * Cc + co) * C4 + ci] = s;
            }
        }
    }
}

// ---------------- K1: value projection as HMMA GEMM (3-buf pipeline) ------------
#define BUF3 32768
__global__ void __launch_bounds__(512) k_vproj_mma(const float* __restrict__ bias) {
    extern __shared__ char dsm[];
    const uint32_t sbase = smem_u32(dsm);
    const uint32_t offA = 0, offB = 16384;

    const int b = blockIdx.z;
    const int pix0 = blockIdx.x * 128;
    const int t = threadIdx.x;
    const int wid = t >> 5, lane = t & 31;
    const int wm = wid >> 2, wn = wid & 3;

    const __half* __restrict__ wv = g_wv;
    const __half* __restrict__ xh = g_xh + (size_t)b * LLEN * Cc;

    float acc[2][4][4] = {};

    const int aRow = wm * 32 + (lane & 15);
    const int aColHalf = (lane & 16) ? 16 : 0;
    const int bRow = wn * 32 + (lane & 7);
    const int bColHalf = (lane & 8) ? 16 : 0;

    auto stage_load = [&](int s) {
        const uint32_t bufOff = (uint32_t)(s % 3) * BUF3;
        const int k0 = s * 64;
        for (int idx = t; idx < 1024; idx += 512) {
            const int r = idx >> 3, ch = idx & 7;
            const uint32_t sw = swz((uint32_t)(r * 128 + ch * 16));
            const int goff = ch * 8;
            cp16(sbase + bufOff + offA + sw, wv + (size_t)r * Cc + k0 + goff, true);
            cp16(sbase + bufOff + offB + sw, xh + (size_t)(pix0 + r) * Cc + k0 + goff, true);
        }
        cp_commit();
    };

    stage_load(0);
    stage_load(1);

    for (int s = 0; s < 8; s++) {
        if (s < 7) cp_wait1(); else cp_wait0();
        __syncthreads();
        if (s + 2 < 8) stage_load(s + 2);
        const uint32_t bufOff = (uint32_t)(s % 3) * BUF3;
#pragma unroll
        for (int kk = 0; kk < 4; kk++) {
            uint32_t Af[2][4], Bf[4][2];
#pragma unroll
            for (int mt = 0; mt < 2; mt++) {
                const uint32_t boff = swz((uint32_t)((aRow + mt * 16) * 128 + kk * 32 + aColHalf));
                ldsm_x4(Af[mt][0], Af[mt][1], Af[mt][2], Af[mt][3], sbase + bufOff + offA + boff);
            }
#pragma unroll
            for (int nt = 0; nt < 4; nt++) {
                const uint32_t boff = swz((uint32_t)((bRow + nt * 8) * 128 + kk * 32 + bColHalf));
                ldsm_x2(Bf[nt][0], Bf[nt][1], sbase + bufOff + offB + boff);
            }
#pragma unroll
            for (int mt = 0; mt < 2; mt++)
#pragma unroll
                for (int nt = 0; nt < 4; nt++)
                    mma_f16(acc[mt][nt], Af[mt], Bf[nt]);
        }
    }

    const int mBase = wm * 32 + (lane >> 2);
    const int nBase = pix0 + wn * 32 + (lane & 3) * 2;
#pragma unroll
    for (int mt = 0; mt < 2; mt++) {
#pragma unroll
        for (int half = 0; half < 2; half++) {
            const int co = mBase + mt * 16 + half * 8;
            const float bs = bias[co];
#pragma unroll
            for (int nt = 0; nt < 4; nt++) {
                const int l = nBase + nt * 8;
                const __half2 hv = __floats2half2_rn(acc[mt][nt][half * 2] + bs,
                                                     acc[mt][nt][half * 2 + 1] + bs);
                *(__half2*)&g_vh[((size_t)b * C4 + co) * LLEN + l] = hv;
            }
        }
    }
}

// ---------------- K1c: adaptive avg pool to 4x4 (parallel over 128 CTAs) --------
__global__ void k_pool(const float* __restrict__ x) {
    const int b = blockIdx.x, cg = blockIdx.y;
    const int t = threadIdx.x;
    const int c = cg * 64 + (t >> 2);
    const int cellq = (t & 3) * 4;
    const float* xc = x + ((size_t)b * Cc + c) * LLEN;
#pragma unroll
    for (int cq = 0; cq < 4; cq++) {
        const int cell = cellq + cq;
        const int i = cell >> 2, j = cell & 3;
        float s = 0.f;
        for (int y = 0; y < 8; y++) {
            const float* row = &xc[(i * 8 + y) * 32 + j * 8];
#pragma unroll
            for (int xx = 0; xx < 8; xx++) s += row[xx];
        }
        g_sp4[(b * Cc + c) * 16 + cell] = s * (1.f / 64.f);
    }
}

// ---------------- K2: rce + q/k feats + bilinear upsample ----------------------
__global__ void k_prep(const float* __restrict__ rce_b,
                       const float* __restrict__ qw, const float* __restrict__ qb,
                       const float* __restrict__ kw, const float* __restrict__ kb) {
    __shared__ float sp4[Cc * 16];
    __shared__ float f4[C4 * 16];
    __shared__ float f2[C4 * 4];
    __shared__ float pf4[C4 * 16];
    __shared__ float pf2[C4 * 4];
    __shared__ float qf4[QKC * 16], kf4[QKC * 16];
    __shared__ float qf2[QKC * 4],  kf2[QKC * 4];
    const int b = blockIdx.x, t = threadIdx.x;

    for (int idx = t; idx < Cc * 16 / 4; idx += 256)
        *(float4*)&sp4[idx * 4] = *(const float4*)&g_sp4[b * Cc * 16 + idx * 4];
    __syncthreads();

    {
        const int out = t & 127, half = t >> 7;
        const int c0 = half * 256;
        float a4[16] = {}, a2[4] = {};
        for (int c = c0; c < c0 + 256; c++) {
            const float w4 = g_rwT[(Cc + c) * C4 + out];
            const float w2 = g_rwT[c * C4 + out];
            const float* p = &sp4[c * 16];
#pragma unroll
            for (int cell = 0; cell < 16; cell++) a4[cell] = fmaf(w4, p[cell], a4[cell]);
#pragma unroll
            for (int i = 0; i < 2; i++)
#pragma unroll
                for (int j = 0; j < 2; j++)
                    a2[i * 2 + j] = fmaf(w2 * 0.25f,
                        p[(2 * i) * 4 + 2 * j] + p[(2 * i) * 4 + 2 * j + 1] +
                        p[(2 * i + 1) * 4 + 2 * j] + p[(2 * i + 1) * 4 + 2 * j + 1],
                        a2[i * 2 + j]);
        }
        if (half == 1) {
#pragma unroll
            for (int cell = 0; cell < 16; cell++) pf4[out * 16 + cell] = a4[cell];
#pragma unroll
            for (int cc = 0; cc < 4; cc++) pf2[out * 4 + cc] = a2[cc];
        }
        __syncthreads();
        if (half == 0) {
            const float b4 = rce_b[2 * C4 + out], b2v = rce_b[1 * C4 + out];
#pragma unroll
            for (int cell = 0; cell < 16; cell++)
                f4[out * 16 + cell] = a4[cell] + pf4[out * 16 + cell] + b4;
#pragma unroll
            for (int cc = 0; cc < 4; cc++)
                f2[out * 4 + cc] = a2[cc] + pf2[out * 4 + cc] + b2v;
        }
    }
    __syncthreads();

    {
        const int qc = t >> 4, cell = t & 15;
        float aq = 0.f, ak = 0.f;
        for (int o = 0; o < C4; o++) {
            const float fv = f4[o * 16 + cell];
            aq += qw[qc * C4 + o] * fv;
            ak += kw[qc * C4 + o] * fv;
        }
        qf4[t] = aq + qb[qc]; kf4[t] = ak + kb[qc];
    }
    if (t < 64) {
        const int qc = t >> 2, cc = t & 3;
        float aq = 0.f, ak = 0.f;
        for (int o = 0; o < C4; o++) {
            const float fv = f2[o * 4 + cc];
            aq += qw[qc * C4 + o] * fv;
            ak += kw[qc * C4 + o] * fv;
        }
        qf2[t] = aq + qb[qc]; kf2[t] = ak + kb[qc];
    }
    __syncthreads();

    const float st4 = 3.0f / 31.0f, st2 = 1.0f / 31.0f;
    for (int idx = t; idx < QKC * LLEN; idx += 256) {
        const int qc = idx >> 10, p = idx & 1023, r = p >> 5, cc = p & 31;
        float pr = r * st4;  int lr = (int)pr; lr = lr > 2 ? 2 : lr; float fr = pr - lr;
        float pc = cc * st4; int lc = (int)pc; lc = lc > 2 ? 2 : lc; float fc = pc - lc;
        const float w00 = (1.f - fr) * (1.f - fc), w01 = (1.f - fr) * fc;
        const float w10 = fr * (1.f - fc),         w11 = fr * fc;
        const float* q4 = &qf4[qc * 16]; const float* k4 = &kf4[qc * 16];
        g_qk[qk_idx(0, 1, b, qc, p)] =
            w00 * q4[lr * 4 + lc] + w01 * q4[lr * 4 + lc + 1] +
            w10 * q4[(lr + 1) * 4 + lc] + w11 * q4[(lr + 1) * 4 + lc + 1];
        g_qk[qk_idx(1, 1, b, qc, p)] =
            w00 * k4[lr * 4 + lc] + w01 * k4[lr * 4 + lc + 1] +
            w10 * k4[(lr + 1) * 4 + lc] + w11 * k4[(lr + 1) * 4 + lc + 1];
        const float fr2 = r * st2, fc2 = cc * st2;
        const float u00 = (1.f - fr2) * (1.f - fc2), u01 = (1.f - fr2) * fc2;
        const float u10 = fr2 * (1.f - fc2),          u11 = fr2 * fc2;
        const float* q2 = &qf2[qc * 4]; const float* k2 = &kf2[qc * 4];
        g_qk[qk_idx(0, 0, b, qc, p)] = u00 * q2[0] + u01 * q2[1] + u10 * q2[2] + u11 * q2[3];
        g_qk[qk_idx(1, 0, b, qc, p)] = u00 * k2[0] + u01 * k2[1] + u10 * k2[2] + u11 * k2[3];
    }
}

// ---------------- K3: sz=1 pyramid mean (reads fp16 V) -------------------------
__global__ void k_mean() {
    const int c = blockIdx.x, b = blockIdx.y, t = threadIdx.x;
    const __half* v = &g_vh[(b * C4 + c) * LLEN];
    float s = 0.f;
    for (int i = t; i < LLEN; i += 256) s += __half2float(v[i]);
    __shared__ float red[256];
    red[t] = s; __syncthreads();
    for (int o = 128; o > 0; o >>= 1) { if (t < o) red[t] += red[t + o]; __syncthreads(); }
    if (t == 0) g_mean[b * C4 + c] = red[0] * (1.f / LLEN);
}

// ---------------- K3c: constant-channel conv contribution ----------------
__global__ void k_const() {
    __shared__ float sm[C4];
    const int b = blockIdx.x, co = threadIdx.x;
    if (co < C4) sm[co] = g_mean[b * C4 + co];
    __syncthreads();
#pragma unroll
    for (int pat = 0; pat < 9; pat++) {
        const float* ws = &g_wsum[(pat * Cc + co) * C4];
        float s = 0.f;
        for (int ci = 0; ci < C4; ci++) s += sm[ci] * ws[ci];
        g_contrib[(b * 9 + pat) * Cc + co] = s;
    }
}

// ---------------- K4: energy + softmax -> attn probabilities -------------------
__global__ void __launch_bounds__(256, 4) k_attn() {
    extern __shared__ __half ksh[];   // 1024 * 16 halfs = 32KB
    const int b = blockIdx.z, pyr = blockIdx.y;
    const int mbase = blockIdx.x * 128;
    const int t = threadIdx.x, w = t >> 5, lane = t & 31;
    const float* gq = &g_qk[qk_idx(0, pyr, b, 0, 0)];
    const float* gk = &g_qk[qk_idx(1, pyr, b, 0, 0)];
    for (int idx = t; idx < QKC * LLEN; idx += 256) {
        const int qc = idx >> 10, l = idx & 1023;
        const int addr = (l * 16 + qc) ^ ((l & 4) ? 8 : 0);
        ksh[addr] = __float2half(gk[qc * LLEN + l]);
    }
    __syncthreads();
    __half* pb = &g_attnh[(size_t)(pyr * Nn + b) * LLEN * LLEN];

    for (int pr = 0; pr < 16; pr++) {
        const int m = mbase + pr * 8 + w;
        __half2 q2[8];
#pragma unroll
        for (int j = 0; j < 8; j++)
            q2[j] = __floats2half2_rn(gq[(2 * j) * LLEN + m], gq[(2 * j + 1) * LLEN + m]);
        uint32_t e2[16];
        float mx = -1e30f;
        float sprev = 0.f;
#pragma unroll
        for (int i = 0; i < 32; i++) {
            const int l = i * 32 + lane;
            const int hi = (l * 16) ^ ((l & 4) ? 8 : 0);
            const uint4 kA = *(const uint4*)&ksh[hi];
            const uint4 kB = *(const uint4*)&ksh[hi ^ 8];
            const __half2* hA = (const __half2*)&kA;
            const __half2* hB = (const __half2*)&kB;
            __half2 s2 = __float2half2_rn(0.f);
#pragma unroll
            for (int j = 0; j < 4; j++) s2 = __hfma2(q2[j], hA[j], s2);
#pragma unroll
            for (int j = 0; j < 4; j++) s2 = __hfma2(q2[4 + j], hB[j], s2);
            const float2 fs = __half22float2(s2);
            const float s = fs.x + fs.y;
            mx = fmaxf(mx, s);
            if (i & 1) {
                const __half2 pk = __floats2half2_rn(sprev, s);
                e2[i >> 1] = *(const uint32_t*)&pk;
            } else {
                sprev = s;
            }
        }
#pragma unroll
        for (int o = 16; o > 0; o >>= 1)
            mx = fmaxf(mx, __shfl_xor_sync(0xffffffffu, mx, o));
        float sm = 0.f;
#pragma unroll
        for (int i2 = 0; i2 < 16; i2++) {
            const float2 f = __half22float2(*(const __half2*)&e2[i2]);
            const float a = fexp(f.x - mx);
            const float bb = fexp(f.y - mx);
            sm += a + bb;
            const __half2 pk = __floats2half2_rn(a, bb);
            e2[i2] = *(const uint32_t*)&pk;
        }
#pragma unroll
        for (int o = 16; o > 0; o >>= 1)
            sm += __shfl_xor_sync(0xffffffffu, sm, o);
        const float inv = 1.f / sm;
        __half* pa = &pb[(size_t)m * LLEN];
#pragma unroll
        for (int i2 = 0; i2 < 16; i2++) {
            const float2 f = __half22float2(*(const __half2*)&e2[i2]);
            pa[(2 * i2) * 32 + lane]     = __float2half(f.x * inv);
            pa[(2 * i2 + 1) * 32 + lane] = __float2half(f.y * inv);
        }
    }
}

// ---------------- K5: HMMA out-GEMM (3-buf): catT[pix][c] = V·P^T --------------
__global__ void __launch_bounds__(512) k_outgemm_mma() {
    extern __shared__ char dsm[];
    const uint32_t sbase = smem_u32(dsm);
    const uint32_t offA = 0, offB = 16384;

    const int z = blockIdx.z; const int b = z >> 1; const int pyr = z & 1;
    const int pix0 = blockIdx.x * 128;
    const int t = threadIdx.x;
    const int wid = t >> 5, lane = t & 31;
    const int wm = wid >> 2, wn = wid & 3;

    const __half* __restrict__ vh = g_vh + (size_t)b * C4 * LLEN;
    const __half* __restrict__ P  = g_attnh + (size_t)(pyr * Nn + b) * LLEN * LLEN;

    float acc[2][4][4] = {};

    const int aRow = wm * 32 + (lane & 15);
    const int aColHalf = (lane & 16) ? 16 : 0;
    const int bRow = wn * 32 + (lane & 7);
    const int bColHalf = (lane & 8) ? 16 : 0;

    auto stage_load = [&](int s) {
        const uint32_t bufOff = (uint32_t)(s % 3) * BUF3;
        const int l0 = s * 64;
        for (int idx = t; idx < 1024; idx += 512) {
            const int r = idx >> 3, ch = idx & 7;
            const uint32_t sw = swz((uint32_t)(r * 128 + ch * 16));
            const int goff = ch * 8;
            cp16(sbase + bufOff + offA + sw, vh + (size_t)r * LLEN + l0 + goff, true);
            cp16(sbase + bufOff + offB + sw, P + (size_t)(pix0 + r) * LLEN + l0 + goff, true);
        }
        cp_commit();
    };

    stage_load(0);
    stage_load(1);

    for (int s = 0; s < 16; s++) {
        if (s < 15) cp_wait1(); else cp_wait0();
        __syncthreads();
        if (s + 2 < 16) stage_load(s + 2);
        const uint32_t bufOff = (uint32_t)(s % 3) * BUF3;
#pragma unroll
        for (int kk = 0; kk < 4; kk++) {
            uint32_t Af[2][4], Bf[4][2];
#pragma unroll
            for (int mt = 0; mt < 2; mt++) {
                const uint32_t boff = swz((uint32_t)((aRow + mt * 16) * 128 + kk * 32 + aColHalf));
                ldsm_x4(Af[mt][0], Af[mt][1], Af[mt][2], Af[mt][3], sbase + bufOff + offA + boff);
            }
#pragma unroll
            for (int nt = 0; nt < 4; nt++) {
                const uint32_t boff = swz((uint32_t)((bRow + nt * 8) * 128 + kk * 32 + bColHalf));
                ldsm_x2(Bf[nt][0], Bf[nt][1], sbase + bufOff + offB + boff);
            }
#pragma unroll
            for (int mt = 0; mt < 2; mt++)
#pragma unroll
                for (int nt = 0; nt < 4; nt++)
                    mma_f16(acc[mt][nt], Af[mt], Bf[nt]);
        }
    }
    __syncthreads();

    // epilogue: smem transpose [pixLocal][c] (pitch 136), then coalesced fp16 store
    __half* eb = (__half*)dsm;
    const int cBase = wm * 32 + (lane >> 2);
    const int pBase = wn * 32 + (lane & 3) * 2;
#pragma unroll
    for (int mt = 0; mt < 2; mt++)
#pragma unroll
        for (int half = 0; half < 2; half++) {
            const int c = cBase + mt * 16 + half * 8;
#pragma unroll
            for (int nt = 0; nt < 4; nt++)
#pragma unroll
                for (int e = 0; e < 2; e++) {
                    const int p = pBase + nt * 8 + e;
                    eb[p * 136 + c] = __float2half(acc[mt][nt][half * 2 + e]);
                }
        }
    __syncthreads();
    for (int idx = t; idx < 128 * 16; idx += 512) {
        const int row = idx >> 4, ch = idx & 15;
        const uint4 v = *(const uint4*)&eb[row * 136 + ch * 8];
        *(uint4*)&g_cth[((size_t)(b * LLEN + pix0 + row)) * 256 + pyr * C4 + ch * 8] = v;
    }
}

// ---------------- K6: fusion conv as fp16 HMMA GEMM (3-buf pipeline) -----------
__global__ void __launch_bounds__(512) k_conv_mma() {
    extern __shared__ char dsm[];
    const uint32_t sbase = smem_u32(dsm);
    const uint32_t offA = 0, offB = 16384;

    const int b = blockIdx.z;
    const int co0 = blockIdx.y * 128;
    const int pix0 = blockIdx.x * 128;
    const int t = threadIdx.x;
    const int wid = t >> 5, lane = t & 31;
    const int wm = wid >> 2, wn = wid & 3;

    const __half* __restrict__ wh = g_wh;
    const __half* __restrict__ cth = g_cth + (size_t)b * LLEN * 256;

    float acc[2][4][4] = {};

    const int aRow = wm * 32 + (lane & 15);
    const int aColHalf = (lane & 16) ? 16 : 0;
    const int bRow = wn * 32 + (lane & 7);
    const int bColHalf = (lane & 8) ? 16 : 0;

    auto stage_load = [&](int s) {
        const uint32_t bufOff = (uint32_t)(s % 3) * BUF3;
        const int tap = s >> 2;
        const int ky = tap / 3, kx = tap - ky * 3;
        const int ci0 = (s & 3) * 64;
        const int kA = s * 64;
        for (int idx = t; idx < 1024; idx += 512) {
            const int r = idx >> 3, ch = idx & 7;
            const uint32_t sw = swz((uint32_t)(r * 128 + ch * 16));
            const int goff = ch * 8;
            cp16(sbase + bufOff + offA + sw, wh + (size_t)(co0 + r) * CONVK + kA + goff, true);
            const int gp = pix0 + r;
            const int sy = (gp >> 5) + ky - 1, sx = (gp & 31) + kx - 1;
            const bool ok = (sy >= 0 && sy < 32 && sx >= 0 && sx < 32);
            const __half* src = ok ? (cth + ((size_t)(sy * 32 + sx)) * 256 + ci0 + goff) : cth;
            cp16(sbase + bufOff + offB + sw, src, ok);
        }
        cp_commit();
    };

    stage_load(0);
    stage_load(1);

    for (int s = 0; s < 36; s++) {
        if (s < 35) cp_wait1(); else cp_wait0();
        __syncthreads();
        if (s + 2 < 36) stage_load(s + 2);
        const uint32_t bufOff = (uint32_t)(s % 3) * BUF3;
#pragma unroll
        for (int kk = 0; kk < 4; kk++) {
            uint32_t Af[2][4], Bf[4][2];
#pragma unroll
            for (int mt = 0; mt < 2; mt++) {
                const uint32_t boff = swz((uint32_t)((aRow + mt * 16) * 128 + kk * 32 + aColHalf));
                ldsm_x4(Af[mt][0], Af[mt][1], Af[mt][2], Af[mt][3], sbase + bufOff + offA + boff);
            }
#pragma unroll
            for (int nt = 0; nt < 4; nt++) {
                const uint32_t boff = swz((uint32_t)((bRow + nt * 8) * 128 + kk * 32 + bColHalf));
                ldsm_x2(Bf[nt][0], Bf[nt][1], sbase + bufOff + offB + boff);
            }
#pragma unroll
            for (int mt = 0; mt < 2; mt++)
#pragma unroll
                for (int nt = 0; nt < 4; nt++)
                    mma_f16(acc[mt][nt], Af[mt], Bf[nt]);
        }
    }

    const float* cbp = &g_contrib[(size_t)b * 9 * Cc];
    const int mBase = co0 + wm * 32 + (lane >> 2);
    const int nBase = pix0 + wn * 32 + (lane & 3) * 2;
#pragma unroll
    for (int mt = 0; mt < 2; mt++) {
#pragma unroll
        for (int half = 0; half < 2; half++) {
            const int co = mBase + mt * 16 + half * 8;
            float* yrow = &g_y[((size_t)b * Cc + co) * LLEN];
#pragma unroll
            for (int nt = 0; nt < 4; nt++) {
#pragma unroll
                for (int e = 0; e < 2; e++) {
                    const int gp = nBase + nt * 8 + e;
                    const int y = gp >> 5, xg = gp & 31;
                    const int rt = (y == 0) ? 0 : ((y == 31) ? 2 : 1);
                    const int ct = (xg == 0) ? 0 : ((xg == 31) ? 2 : 1);
                    const float cc = cbp[(rt * 3 + ct) * Cc + co];
                    yrow[gp] = acc[mt][nt][half * 2 + e] + cc;
                }
            }
        }
    }
}

// ---------------- K7: BN batch statistics (fp32 partials) ----------------------
__global__ void k_stats(const float* __restrict__ bn_scale) {
    const int c = blockIdx.x, t = threadIdx.x;
    float s = 0.f, ss = 0.f;
    for (int idx = t; idx < Nn * LLEN; idx += 256) {
        const int bb = idx >> 10, l = idx & 1023;
        const float v = g_y[((size_t)bb * Cc + c) * LLEN + l];
        s += v; ss = fmaf(v, v, ss);
    }
    __shared__ float rs[256], rq[256];
    rs[t] = s; rq[t] = ss; __syncthreads();
    for (int o = 128; o > 0; o >>= 1) {
        if (t < o) { rs[t] += rs[t + o]; rq[t] += rq[t + o]; }
        __syncthreads();
    }
    if (t == 0) {
        const float mean = rs[0] * (1.f / (Nn * LLEN));
        float var = rq[0] * (1.f / (Nn * LLEN)) - mean * mean;
        var = fmaxf(var, 0.f);
        g_stats[c * 2]     = mean;
        g_stats[c * 2 + 1] = bn_scale[c] * rsqrtf(var + EPSf);
    }
}

// ---------------- K8: BN apply + ReLU + gamma*y + x ----------------------------
__global__ void k_final(const float* __restrict__ x, const float* __restrict__ bn_bias,
                        const float* __restrict__ gamma, float* __restrict__ out) {
    const int idx = blockIdx.x * 256 + threadIdx.x;
    const float g = gamma[0];
    const int c = (idx >> 10) & (Cc - 1);
    const float v = g_y[idx];
    float tt = (v - g_stats[c * 2]) * g_stats[c * 2 + 1] + bn_bias[c];
    tt = fmaxf(tt, 0.f);
    out[idx] = g * tt + x[idx];
}

// ---------------- launch ------------------------------------------------------
extern "C" void kernel_launch(void* const* d_in, const int* in_sizes, int n_in,
                              void* d_out, int out_size) {
    (void)in_sizes; (void)n_in; (void)out_size;
    const float* x        = (const float*)d_in[0];
    const float* rce_w    = (const float*)d_in[1];
    const float* rce_b    = (const float*)d_in[2];
    const float* q_w      = (const float*)d_in[3];
    const float* q_b      = (const float*)d_in[4];
    const float* k_w      = (const float*)d_in[5];
    const float* k_b      = (const float*)d_in[6];
    const float* value_w  = (const float*)d_in[7];
    const float* value_b  = (const float*)d_in[8];
    const float* fusion_w = (const float*)d_in[9];
    const float* bn_scale = (const float*)d_in[10];
    const float* bn_bias  = (const float*)d_in[11];
    const float* gamma    = (const float*)d_in[12];
    float* out = (float*)d_out;

    cudaFuncSetAttribute(k_attn, cudaFuncAttributeMaxDynamicSharedMemorySize, 32768);
    cudaFuncSetAttribute(k_conv_mma, cudaFuncAttributeMaxDynamicSharedMemorySize, 98304);
    cudaFuncSetAttribute(k_outgemm_mma, cudaFuncAttributeMaxDynamicSharedMemorySize, 98304);
    cudaFuncSetAttribute(k_vproj_mma, cudaFuncAttributeMaxDynamicSharedMemorySize, 98304);

    // Launch #4 (ncu capture slot) = k_attn — verify the R12 attn rewrite.
    k_pool<<<dim3(16, 8), 256>>>(x);
    k_wprep<<<5632, 256>>>(value_w, rce_w, fusion_w);
    k_prep<<<16, 256>>>(rce_b, q_w, q_b, k_w, k_b);
    k_attn<<<dim3(8, 2, 16), 256, 32768>>>();
    k_xh<<<dim3(32, 16, 16), 256>>>(x);
    k_vproj_mma<<<dim3(8, 1, 16), 512, 98304>>>(value_b);
    k_outgemm_mma<<<dim3(8, 1, 32), 512, 98304>>>();
    k_mean<<<dim3(128, 16), 256>>>();
    k_const<<<16, 512>>>();
    k_conv_mma<<<dim3(8, 4, 16), 512, 98304>>>();
    k_stats<<<512, 256>>>(bn_scale);
    k_final<<<32768, 256>>>(x, bn_bias, gamma, out);
}